// round 8
// baseline (speedup 1.0000x reference)
#include <cuda_runtime.h>
#include <cuda_bf16.h>

// RITS recurrence v7: 3 barriers/step (minimum: one per all-to-all GEMM).
//  - 128 CTAs x 256 thr, 2 samples/CTA, T=512 on-chip.
//  - P1: x_hat / gamma_h GEMMs, kh=lane>>4 (wavefront-aligned), shfl_xor 16,
//    fused epilogue -> xc/gx/m (chunked act) + hdec + xhat.
//  - P2: z_hat + beta GEMMs fused per thread (kq=lane&3), bank-padded weight
//    regions + chunked act, shfl_xor 1,2 -> local beta/c_hat/c_c epilogue.
//  - P3: v6 phase C (register weights, kc lane-split on padded actC chunks).

#define TT 512
#define NIMP (256L * 3 * 512 * 64)
typedef unsigned long long ull;

#define FMA2(acc, a, b) \
    asm("fma.rn.f32x2 %0, %1, %2, %0;" : "+l"(acc) : "l"(a), "l"(b))

__device__ __forceinline__ ull pk2(float x, float y) {
    ull r; asm("mov.b64 %0, {%1, %2};" : "=l"(r) : "f"(x), "f"(y)); return r;
}
__device__ __forceinline__ float2 upk(ull v) {
    float2 r; asm("mov.b64 {%0, %1}, %2;" : "=f"(r.x), "=f"(r.y) : "l"(v)); return r;
}
__device__ __forceinline__ float sigf(float x) { return 1.f / (1.f + __expf(-x)); }

__global__ __launch_bounds__(256, 1) void rits_kernel(
    const float* __restrict__ inputs,
    const float* __restrict__ W_hist, const float* __restrict__ b_hist,
    const float* __restrict__ W_feat, const float* __restrict__ b_feat,
    const float* __restrict__ W_gx,   const float* __restrict__ b_gx,
    const float* __restrict__ W_gh,   const float* __restrict__ b_gh,
    const float* __restrict__ W_beta, const float* __restrict__ b_beta,
    const float* __restrict__ W_lstm, const float* __restrict__ U_lstm,
    const float* __restrict__ b_lstm,
    const float* __restrict__ W_out,  const float* __restrict__ b_out,
    float* __restrict__ out)
{
    extern __shared__ __align__(16) float sm[];
    float* sWh2  = sm;             // 4096  W_hist pairs {w[2q][j],w[2q+1][j]}
    float* sWgh2 = sWh2  + 4096;   // 4096  W_gh pairs
    float* sWf2  = sWgh2 + 4096;   // 4128  W_feat_c pairs, 4 regions of 516 f2
    float* sWb2  = sWf2  + 4128;   // 8224  W_beta pairs, 4 regions of 1028 f2
    float* sWgx  = sWb2  + 8224;   // 64    diag(W_gx)
    float* sbh   = sWgx + 64;
    float* sbf   = sbh  + 64;
    float* sbgx  = sbf  + 64;
    float* sbb   = sbgx + 64;
    float* sbgh  = sbb  + 64;
    float* hS    = sbgh + 64;      // 128  h [s*64+j]
    float* cS    = hS   + 128;     // 128
    float* xhat  = cS   + 128;     // 128  [s*64+j]
    float* sact  = xhat + 128;     // 512  per sample 256:
                                   //   [ xc: 4 chunks{16 data+8 pad} (96) |
                                   //     gx|m: 4 chunks{32 data+8 pad} (160) ]
    float* actC  = sact + 512;     // 400  P3 chunks (s,kc) x 100
    float* inb   = actC + 400;     // 2*384 double-buffered [c*128 + s*64 + k]

    const int tid  = threadIdx.x;
    const int bid  = blockIdx.x;
    const int lane = tid & 31;
    const int w    = tid >> 5;

    // ---- pack smem weights ----
    for (int i = tid; i < 2048; i += 256) {
        int q = i >> 6, j = i & 63;
        *(float2*)&sWh2[i * 2]  = make_float2(W_hist[(2*q)*64 + j], W_hist[(2*q+1)*64 + j]);
        *(float2*)&sWgh2[i * 2] = make_float2(W_gh[(2*q)*64 + j],   W_gh[(2*q+1)*64 + j]);
    }
    for (int i = tid; i < 2048; i += 256) {       // W_feat_c, kq-region layout
        int q = i >> 6, j = i & 63;
        float a = (2*q     == j) ? 0.f : W_feat[(2*q)*64 + j];
        float b = (2*q + 1 == j) ? 0.f : W_feat[(2*q+1)*64 + j];
        int idx = (q >> 3) * 516 + (q & 7) * 64 + j;
        *(float2*)&sWf2[idx * 2] = make_float2(a, b);
    }
    for (int i = tid; i < 4096; i += 256) {       // W_beta, kq-region layout
        int q = i >> 6, j = i & 63;
        int idx = (q >> 4) * 1028 + (q & 15) * 64 + j;
        *(float2*)&sWb2[idx * 2] = make_float2(W_beta[(2*q)*64 + j], W_beta[(2*q+1)*64 + j]);
    }
    if (tid < 64) {
        sWgx[tid] = W_gx[tid * 64 + tid];
        sbh[tid]  = b_hist[tid];
        sbf[tid]  = b_feat[tid];
        sbgx[tid] = b_gx[tid];
        sbb[tid]  = b_beta[tid];
        sbgh[tid] = b_gh[tid];
    }
    if (tid < 128) { hS[tid] = 0.f; cS[tid] = 0.f; }

    // ---- P3 register weights (v6): lane = jl*4 + gp*2 + kc ----
    const int kcC = lane & 1;
    const int gpC = (lane >> 1) & 1;
    const int jCc = w * 8 + (lane >> 2);
    const int colA = gpC * 64 + jCc;
    const int colB = colA + 128;
    ull wA[48], wB[48];
#pragma unroll
    for (int u = 0; u < 48; u++) {
        int pr = kcC * 48 + u;
        int r0 = 2 * pr, r1 = r0 + 1;
        float a0 = (r0 < 128) ? W_lstm[r0 * 256 + colA] : U_lstm[(r0 - 128) * 256 + colA];
        float a1 = (r1 < 128) ? W_lstm[r1 * 256 + colA] : U_lstm[(r1 - 128) * 256 + colA];
        float b0 = (r0 < 128) ? W_lstm[r0 * 256 + colB] : U_lstm[(r0 - 128) * 256 + colB];
        float b1 = (r1 < 128) ? W_lstm[r1 * 256 + colB] : U_lstm[(r1 - 128) * 256 + colB];
        wA[u] = pk2(a0, a1);
        wB[u] = pk2(b0, b1);
    }
    const float blA = b_lstm[colA];
    const float blB = b_lstm[colB];

    // ---- input loader mapping (threads 0..191) ----
    const int ls = tid / 96;
    const int lr = tid % 96;
    const int lc = lr / 32;             // 0=x 1=m 2=d
    const int ll = lr % 32;
    const long lbase = ((long)(2 * bid + ls) * 3 + lc) * TT * 64;

    if (tid < 192) {
        float2 v = *(const float2*)&inputs[lbase + 2 * ll];
        *(float2*)&inb[lc * 128 + ls * 64 + 2 * ll] = v;
    }
    __syncthreads();

    // ---- P1 / P2 lane decompositions ----
    const int jobA = w * 16 + (lane & 15);   // [0,128): g*64 + j
    const int khA  = lane >> 4;              // wavefront-aligned k-half
    const int gA   = jobA >> 6;              // warp-uniform
    const int jA   = jobA & 63;
    const int kqB  = lane & 3;               // P2 k-quarter (bank-padded)
    const int jB   = w * 8 + (lane >> 2);    // [0,64)

    int p = 0;
    for (int t = 0; t < TT; t++) {
        float* bufc = inb + p * 384;

        float2 pf = make_float2(0.f, 0.f);
        if (tid < 192 && t + 1 < TT)
            pf = *(const float2*)&inputs[lbase + (long)(t + 1) * 64 + 2 * ll];

        // ===== P1: x_hat pre (h@W_hist) | gamma_h pre (d@W_gh), shfl reduce ==
        {
            const float* act = gA ? (bufc + 256) : hS;
            const float* W   = gA ? sWgh2 : sWh2;
            ull acc0 = 0, acc1 = 0;
#pragma unroll
            for (int i = 0; i < 8; i++) {
                int k = khA * 32 + 4 * i, q = k >> 1;
                ulonglong2 a0 = *(const ulonglong2*)&act[k];
                ulonglong2 a1 = *(const ulonglong2*)&act[64 + k];
                ull wa = *(const ull*)&W[(q * 64 + jA) * 2];
                ull wb = *(const ull*)&W[((q + 1) * 64 + jA) * 2];
                FMA2(acc0, wa, a0.x); FMA2(acc0, wb, a0.y);
                FMA2(acc1, wa, a1.x); FMA2(acc1, wb, a1.y);
            }
            float2 r0 = upk(acc0), r1 = upk(acc1);
            float v0 = r0.x + r0.y, v1 = r1.x + r1.y;
            v0 += __shfl_xor_sync(0xffffffffu, v0, 16);
            v1 += __shfl_xor_sync(0xffffffffu, v1, 16);
            if (lane < 16) {
                int j = jA;
                if (gA == 0) {
                    float xh0 = v0 + sbh[j], xh1 = v1 + sbh[j];
                    xhat[j]      = xh0;
                    xhat[64 + j] = xh1;
                    float x0 = bufc[j],      m0 = bufc[128 + j], d0 = bufc[256 + j];
                    float x1 = bufc[64 + j], m1 = bufc[192 + j], d1 = bufc[320 + j];
                    int xcA = (j >> 4) * 24 + (j & 15);            // xc chunk
                    int gxA = 96 + (j >> 5) * 40 + (j & 31);       // gx chunk
                    int mA  = gxA + 80;                            // m chunk
                    sact[xcA]       = m0 * x0 + (1.f - m0) * xh0;
                    sact[256 + xcA] = m1 * x1 + (1.f - m1) * xh1;
                    sact[gxA]       = __expf(-fmaxf(d0 * sWgx[j] + sbgx[j], 0.f));
                    sact[256 + gxA] = __expf(-fmaxf(d1 * sWgx[j] + sbgx[j], 0.f));
                    sact[mA]        = m0;
                    sact[256 + mA]  = m1;
                    long n0 = 2 * bid, n1 = n0 + 1;
                    out[((n0 * 3 + 0) * (long)TT + t) * 64 + j] = xh0;
                    out[((n1 * 3 + 0) * (long)TT + t) * 64 + j] = xh1;
                } else {
                    float gh0 = __expf(-fmaxf(v0 + sbgh[j], 0.f));
                    float gh1 = __expf(-fmaxf(v1 + sbgh[j], 0.f));
                    actC[100 + 32 + j]       = hS[j]      * gh0;   // chunk (0,1)
                    actC[300 + 32 + j]       = hS[64 + j] * gh1;   // chunk (1,1)
                }
            }
        }
        __syncthreads();

        // ===== P2: z_hat (xc@W_feat_c) + beta ([gx;m]@W_beta), fused/thread ==
        {
            ull z0 = 0, z1 = 0, b0 = 0, b1 = 0;
#pragma unroll
            for (int i = 0; i < 4; i++) {            // z: 8 pairs (kq region)
                ulonglong2 a0 = *(const ulonglong2*)&sact[kqB * 24 + 4 * i];
                ulonglong2 a1 = *(const ulonglong2*)&sact[256 + kqB * 24 + 4 * i];
                ull wa = *(const ull*)&sWf2[(kqB * 516 + (2*i)   * 64 + jB) * 2];
                ull wb = *(const ull*)&sWf2[(kqB * 516 + (2*i+1) * 64 + jB) * 2];
                FMA2(z0, wa, a0.x); FMA2(z0, wb, a0.y);
                FMA2(z1, wa, a1.x); FMA2(z1, wb, a1.y);
            }
#pragma unroll
            for (int i = 0; i < 8; i++) {            // beta: 16 pairs
                ulonglong2 a0 = *(const ulonglong2*)&sact[96 + kqB * 40 + 4 * i];
                ulonglong2 a1 = *(const ulonglong2*)&sact[256 + 96 + kqB * 40 + 4 * i];
                ull wa = *(const ull*)&sWb2[(kqB * 1028 + (2*i)   * 64 + jB) * 2];
                ull wb = *(const ull*)&sWb2[(kqB * 1028 + (2*i+1) * 64 + jB) * 2];
                FMA2(b0, wa, a0.x); FMA2(b0, wb, a0.y);
                FMA2(b1, wa, a1.x); FMA2(b1, wb, a1.y);
            }
            float2 rz0 = upk(z0), rz1 = upk(z1), rb0 = upk(b0), rb1 = upk(b1);
            float zv0 = rz0.x + rz0.y, zv1 = rz1.x + rz1.y;
            float bv0 = rb0.x + rb0.y, bv1 = rb1.x + rb1.y;
#pragma unroll
            for (int off = 1; off <= 2; off <<= 1) {
                zv0 += __shfl_xor_sync(0xffffffffu, zv0, off);
                zv1 += __shfl_xor_sync(0xffffffffu, zv1, off);
                bv0 += __shfl_xor_sync(0xffffffffu, bv0, off);
                bv1 += __shfl_xor_sync(0xffffffffu, bv1, off);
            }
            if (kqB == 0) {
                int j = jB;
                float zh0 = zv0 + sbf[j], zh1 = zv1 + sbf[j];
                float be0 = sigf(bv0 + sbb[j]);
                float be1 = sigf(bv1 + sbb[j]);
                float ch0 = be0 * zh0 + (1.f - be0) * xhat[j];
                float ch1 = be1 * zh1 + (1.f - be1) * xhat[64 + j];
                float x0 = bufc[j],      m0 = bufc[128 + j];
                float x1 = bufc[64 + j], m1 = bufc[192 + j];
                actC[j]       = m0 * x0 + (1.f - m0) * ch0;     // cc chunk (s,0)
                actC[200 + j] = m1 * x1 + (1.f - m1) * ch1;
                if (j < 32) { actC[64 + j]        = m0; actC[264 + j]        = m1; }
                else        { actC[100 + (j-32)]  = m0; actC[300 + (j-32)]  = m1; }
                long n0 = 2 * bid, n1 = n0 + 1;
                out[((n0 * 3 + 1) * (long)TT + t) * 64 + j] = zh0;
                out[((n1 * 3 + 1) * (long)TT + t) * 64 + j] = zh1;
                out[((n0 * 3 + 2) * (long)TT + t) * 64 + j] = ch0;
                out[((n1 * 3 + 2) * (long)TT + t) * 64 + j] = ch1;
            }
        }
        __syncthreads();

        // ===== P3: z = [cc;m;hdec] @ [W_lstm;U], regs, kc lane-split (v6) ====
        {
            ull aA0 = 0, aA1 = 0, aB0 = 0, aB1 = 0;
            const float* c0 = actC + kcC * 100;          // sample 0, own k-half
            const float* c1 = actC + 200 + kcC * 100;    // sample 1
#pragma unroll
            for (int q = 0; q < 24; q++) {
                ulonglong2 L0 = *(const ulonglong2*)&c0[4 * q];
                ulonglong2 L1 = *(const ulonglong2*)&c1[4 * q];
                FMA2(aA0, wA[2*q], L0.x); FMA2(aA0, wA[2*q+1], L0.y);
                FMA2(aB0, wB[2*q], L0.x); FMA2(aB0, wB[2*q+1], L0.y);
                FMA2(aA1, wA[2*q], L1.x); FMA2(aA1, wA[2*q+1], L1.y);
                FMA2(aB1, wB[2*q], L1.x); FMA2(aB1, wB[2*q+1], L1.y);
            }
            float2 r;
            r = upk(aA0); float vA0 = r.x + r.y;
            r = upk(aA1); float vA1 = r.x + r.y;
            r = upk(aB0); float vB0 = r.x + r.y;
            r = upk(aB1); float vB1 = r.x + r.y;
            vA0 += __shfl_xor_sync(0xffffffffu, vA0, 1);
            vA1 += __shfl_xor_sync(0xffffffffu, vA1, 1);
            vB0 += __shfl_xor_sync(0xffffffffu, vB0, 1);
            vB1 += __shfl_xor_sync(0xffffffffu, vB1, 1);
            vA0 += blA; vA1 += blA; vB0 += blB; vB1 += blB;
            float pA0 = __shfl_xor_sync(0xffffffffu, vA0, 2);
            float pA1 = __shfl_xor_sync(0xffffffffu, vA1, 2);
            float pB0 = __shfl_xor_sync(0xffffffffu, vB0, 2);
            float pB1 = __shfl_xor_sync(0xffffffffu, vB1, 2);
            if ((lane & 3) == 0) {
                float cn0 = sigf(pA0) * cS[jCc]      + sigf(vA0) * tanhf(vB0);
                float cn1 = sigf(pA1) * cS[64 + jCc] + sigf(vA1) * tanhf(vB1);
                cS[jCc]      = cn0;
                cS[64 + jCc] = cn1;
                hS[jCc]      = sigf(pB0) * tanhf(cn0);
                hS[64 + jCc] = sigf(pB1) * tanhf(cn1);
            }
        }
        if (tid < 192 && t + 1 < TT)
            *(float2*)&inb[(p ^ 1) * 384 + lc * 128 + ls * 64 + 2 * ll] = pf;
        p ^= 1;
        __syncthreads();
    }

    // ===== predictions: sigmoid(h_last @ W_out + b_out) =====
    if (tid < 64) {
        int s = tid >> 5, l = tid & 31;
        float v = hS[s * 64 + l] * W_out[l] + hS[s * 64 + 32 + l] * W_out[32 + l];
#pragma unroll
        for (int off = 16; off; off >>= 1)
            v += __shfl_down_sync(0xffffffffu, v, off);
        if (l == 0)
            out[NIMP + 2 * bid + s] = 1.f / (1.f + __expf(-(v + b_out[0])));
    }
}

extern "C" void kernel_launch(void* const* d_in, const int* in_sizes, int n_in,
                              void* d_out, int out_size)
{
    const float* inputs = (const float*)d_in[0];
    const float* W_hist = (const float*)d_in[1];
    const float* b_hist = (const float*)d_in[2];
    const float* W_feat = (const float*)d_in[3];
    const float* b_feat = (const float*)d_in[4];
    const float* W_gx   = (const float*)d_in[5];
    const float* b_gx   = (const float*)d_in[6];
    const float* W_gh   = (const float*)d_in[7];
    const float* b_gh   = (const float*)d_in[8];
    const float* W_beta = (const float*)d_in[9];
    const float* b_beta = (const float*)d_in[10];
    const float* W_lstm = (const float*)d_in[11];
    const float* U_lstm = (const float*)d_in[12];
    const float* b_lstm = (const float*)d_in[13];
    const float* W_out  = (const float*)d_in[14];
    const float* b_out  = (const float*)d_in[15];

    const int smem_bytes = 22992 * (int)sizeof(float);   // 91,968 B
    cudaFuncSetAttribute(rits_kernel,
                         cudaFuncAttributeMaxDynamicSharedMemorySize, smem_bytes);

    rits_kernel<<<128, 256, smem_bytes>>>(
        inputs, W_hist, b_hist, W_feat, b_feat, W_gx, b_gx, W_gh, b_gh,
        W_beta, b_beta, W_lstm, U_lstm, b_lstm, W_out, b_out,
        (float*)d_out);
}

// round 9
// speedup vs baseline: 1.1149x; 1.1149x over previous
#include <cuda_runtime.h>

// RITS recurrence v8: 3 barriers/step, all LDS conflict-free by construction.
//  - 128 CTAs x 256 thr, 2 samples/CTA, T=512 on-chip.
//  - P1: x_hat/gamma_h GEMMs; float4 weights; h/d act arrays bank-padded
//    (32+8 halves, stride 40); shfl_xor 16; sample-split epilogue.
//  - P2: z_hat+beta fused; weights pre-swizzled per-(warp,iter,lane) float4
//    slabs (contiguous 512B per LDS.128 -> bytes-floor, zero conflicts);
//    acts in bank-staggered kq chunks; shfl_xor 1,2; kq<2 sample-split epilogue.
//  - P3: 4-way kq split, all 4 gates per thread (96 ull reg weights,
//    4 accums, per-sample passes); padded 56-float act chunks; no gate shfl.

#define TT 512
#define NIMP (256L * 3 * 512 * 64)
typedef unsigned long long ull;

#define FMA2(acc, a, b) \
    asm("fma.rn.f32x2 %0, %1, %2, %0;" : "+l"(acc) : "l"(a), "l"(b))

__device__ __forceinline__ ull pk2(float x, float y) {
    ull r; asm("mov.b64 %0, {%1, %2};" : "=l"(r) : "f"(x), "f"(y)); return r;
}
__device__ __forceinline__ float2 upk(ull v) {
    float2 r; asm("mov.b64 {%0, %1}, %2;" : "=f"(r.x), "=f"(r.y) : "l"(v)); return r;
}
__device__ __forceinline__ float sigf(float x) { return 1.f / (1.f + __expf(-x)); }

__global__ __launch_bounds__(256, 1) void rits_kernel(
    const float* __restrict__ inputs,
    const float* __restrict__ W_hist, const float* __restrict__ b_hist,
    const float* __restrict__ W_feat, const float* __restrict__ b_feat,
    const float* __restrict__ W_gx,   const float* __restrict__ b_gx,
    const float* __restrict__ W_gh,   const float* __restrict__ b_gh,
    const float* __restrict__ W_beta, const float* __restrict__ b_beta,
    const float* __restrict__ W_lstm, const float* __restrict__ U_lstm,
    const float* __restrict__ b_lstm,
    const float* __restrict__ W_out,  const float* __restrict__ b_out,
    float* __restrict__ out)
{
    extern __shared__ __align__(16) float sm[];
    float* sWh4  = sm;             // 4096  W_hist float4 [(k/4)*64+j]
    float* sWgh4 = sWh4  + 4096;   // 4096  W_gh float4
    float* sWzb4 = sWgh4 + 4096;   // 12288 P2 fused weights, per-warp slabs
    float* sWgx  = sWzb4 + 12288;  // 64    diag(W_gx)
    float* sbh   = sWgx + 64;
    float* sbf   = sbh  + 64;
    float* sbgx  = sbf  + 64;
    float* sbb   = sbgx + 64;
    float* sbgh  = sbb  + 64;
    float* hSp   = sbgh + 64;      // 160  h padded [s*80 + jpad]
    float* cS    = hSp  + 160;     // 128
    float* xhat  = cS   + 128;     // 128  [s*64+j]
    float* sact  = xhat + 128;     // 512  per s 256: xc 4x24 | gx/m 4x40
    float* actC  = sact + 512;     // 448  per s 224: 4 chunks of 48+8 pad
    float* inb   = actC + 448;     // 2*416: x[128] m[128] d padded 2x80

    const int tid  = threadIdx.x;
    const int bid  = blockIdx.x;
    const int lane = tid & 31;
    const int w    = tid >> 5;

    // ---- pack P1 weights as float4 [(k/4)*64 + j] ----
    for (int idx = tid; idx < 1024; idx += 256) {
        int q2 = idx >> 6, j = idx & 63, k = 4 * q2;
        ((float4*)sWh4)[idx]  = make_float4(W_hist[k*64+j], W_hist[(k+1)*64+j],
                                            W_hist[(k+2)*64+j], W_hist[(k+3)*64+j]);
        ((float4*)sWgh4)[idx] = make_float4(W_gh[k*64+j], W_gh[(k+1)*64+j],
                                            W_gh[(k+2)*64+j], W_gh[(k+3)*64+j]);
    }
    // ---- pack P2 fused weights into per-(warp,iter,lane) float4 slabs ----
    for (int idx = tid; idx < 3072; idx += 256) {
        int ww = idx / 384, r = idx % 384, it = r >> 5, l = r & 31;
        int jl = l >> 2, kq = l & 3, j = ww * 8 + jl;
        float4 v;
        if (it < 4) {                       // z region: W_feat_c, k0 = kq*16+4it
            int k0 = kq * 16 + 4 * it;
            v.x = (k0     == j) ? 0.f : W_feat[(k0    )*64 + j];
            v.y = (k0 + 1 == j) ? 0.f : W_feat[(k0 + 1)*64 + j];
            v.z = (k0 + 2 == j) ? 0.f : W_feat[(k0 + 2)*64 + j];
            v.w = (k0 + 3 == j) ? 0.f : W_feat[(k0 + 3)*64 + j];
        } else {                            // beta region: W_beta, k0 = kq*32+4it'
            int k0 = kq * 32 + 4 * (it - 4);
            v = make_float4(W_beta[k0*64+j], W_beta[(k0+1)*64+j],
                            W_beta[(k0+2)*64+j], W_beta[(k0+3)*64+j]);
        }
        ((float4*)sWzb4)[idx] = v;
    }
    if (tid < 64) {
        sWgx[tid] = W_gx[tid * 64 + tid];
        sbh[tid]  = b_hist[tid];
        sbf[tid]  = b_feat[tid];
        sbgx[tid] = b_gx[tid];
        sbb[tid]  = b_beta[tid];
        sbgh[tid] = b_gh[tid];
    }
    if (tid < 128) {
        int s = tid >> 6, j = tid & 63;
        hSp[s * 80 + j + ((j >> 5) << 3)] = 0.f;
        cS[tid] = 0.f;
    }

    // ---- P2/P3 shared lane decomposition ----
    const int kq = lane & 3;
    const int jl = lane >> 2;
    const int jP = w * 8 + jl;
    const int jpadP = jP + ((jP >> 5) << 3);

    // ---- P3 register weights: 4 gates x k-quarter of column jP ----
    ull wgr[4][24];
    float bl0, bl1, bl2, bl3;
#pragma unroll
    for (int g = 0; g < 4; g++) {
        int col = g * 64 + jP;
#pragma unroll
        for (int p = 0; p < 24; p++) {
            int r0 = kq * 48 + 2 * p, r1 = r0 + 1;
            float a0 = (r0 < 128) ? W_lstm[r0*256 + col] : U_lstm[(r0-128)*256 + col];
            float a1 = (r1 < 128) ? W_lstm[r1*256 + col] : U_lstm[(r1-128)*256 + col];
            wgr[g][p] = pk2(a0, a1);
        }
    }
    bl0 = b_lstm[jP]; bl1 = b_lstm[64 + jP];
    bl2 = b_lstm[128 + jP]; bl3 = b_lstm[192 + jP];

    // ---- input loader mapping (threads 0..191) ----
    const int ls = tid / 96;
    const int lr = tid % 96;
    const int lc = lr / 32;             // 0=x 1=m 2=d
    const int ll = lr % 32;
    const long lbase = ((long)(2 * bid + ls) * 3 + lc) * TT * 64;
    const int loff = (lc < 2) ? lc * 128 + ls * 64 + 2 * ll
                              : 256 + ls * 80 + 2 * ll + ((2 * ll >= 32) ? 8 : 0);

    if (tid < 192)
        *(float2*)&inb[loff] = *(const float2*)&inputs[lbase + 2 * ll];

    // ---- P1 decomposition ----
    const int jobA = w * 16 + (lane & 15);   // [0,128)
    const int khA  = lane >> 4;              // k-half AND epilogue sample
    const int gA   = jobA >> 6;              // warp-uniform: w<4 -> 0
    const int jA   = jobA & 63;
    const int jpadA = jA + ((jA >> 5) << 3);

    // actC address helper values (compile-time-ish per-thread constants)
    const int fhd = 128 + jA;                               // hdec fused row
    const int hdA = khA * 224 + (fhd / 48) * 56 + (fhd % 48);
    const int xcA = (jA >> 4) * 24 + (jA & 15);
    const int gxA = 96 + (jA >> 5) * 40 + (jA & 31);
    const int mA  = gxA + 80;
    const int ccA = kq * 224 + (jP / 48) * 56 + (jP % 48);           // kq<2
    const int fm2 = 64 + jP;
    const int mmA = kq * 224 + (fm2 / 48) * 56 + (fm2 % 48);         // kq<2

    // per-thread output base pointers
    float* outx = out + (((long)(2 * bid + khA) * 3 + 0) * TT) * 64 + jA;   // gA==0
    float* outz = out + (((long)(2 * bid + kq)  * 3 + 1) * TT) * 64 + jP;   // kq<2
    float* outc = out + (((long)(2 * bid + kq)  * 3 + 2) * TT) * 64 + jP;   // kq<2

    __syncthreads();

    int p = 0;
    for (int t = 0; t < TT; t++) {
        float* bufc = inb + p * 416;

        float2 pf = make_float2(0.f, 0.f);
        if (tid < 192 && t + 1 < TT)
            pf = *(const float2*)&inputs[lbase + (long)(t + 1) * 64 + 2 * ll];

        // ===== P1: x_hat pre (h@W_hist) | gamma_h pre (d@W_gh) =====
        {
            const float* act = gA ? (bufc + 256) : hSp;   // both padded stride-40 halves
            const float* W4  = gA ? sWgh4 : sWh4;
            ull acc0 = 0, acc1 = 0;
#pragma unroll
            for (int i = 0; i < 8; i++) {
                ulonglong2 a0 = *(const ulonglong2*)&act[khA * 40 + 4 * i];
                ulonglong2 a1 = *(const ulonglong2*)&act[80 + khA * 40 + 4 * i];
                ulonglong2 wv = *(const ulonglong2*)&W4[((khA * 8 + i) * 64 + jA) * 4];
                FMA2(acc0, wv.x, a0.x); FMA2(acc0, wv.y, a0.y);
                FMA2(acc1, wv.x, a1.x); FMA2(acc1, wv.y, a1.y);
            }
            float2 r0 = upk(acc0), r1 = upk(acc1);
            float v0 = r0.x + r0.y, v1 = r1.x + r1.y;
            v0 += __shfl_xor_sync(0xffffffffu, v0, 16);
            v1 += __shfl_xor_sync(0xffffffffu, v1, 16);
            float vE = khA ? v1 : v0;                     // my sample's sum
            if (gA == 0) {
                float xh = vE + sbh[jA];
                xhat[khA * 64 + jA] = xh;
                float x = bufc[khA * 64 + jA];
                float m = bufc[128 + khA * 64 + jA];
                float d = bufc[256 + khA * 80 + jpadA];
                sact[khA * 256 + xcA] = m * x + (1.f - m) * xh;
                sact[khA * 256 + gxA] = __expf(-fmaxf(d * sWgx[jA] + sbgx[jA], 0.f));
                sact[khA * 256 + mA]  = m;
                outx[(long)t * 64] = xh;
            } else {
                float gh = __expf(-fmaxf(vE + sbgh[jA], 0.f));
                actC[hdA] = hSp[khA * 80 + jpadA] * gh;
            }
        }
        __syncthreads();

        // ===== P2: z_hat (xc@W_feat_c) + beta ([gx;m]@W_beta) =====
        {
            ull z0 = 0, z1 = 0, b0 = 0, b1 = 0;
#pragma unroll
            for (int i = 0; i < 4; i++) {               // z region
                ulonglong2 a0 = *(const ulonglong2*)&sact[kq * 24 + 4 * i];
                ulonglong2 a1 = *(const ulonglong2*)&sact[256 + kq * 24 + 4 * i];
                ulonglong2 wv = *(const ulonglong2*)&sWzb4[((w * 12 + i) * 32 + lane) * 4];
                FMA2(z0, wv.x, a0.x); FMA2(z0, wv.y, a0.y);
                FMA2(z1, wv.x, a1.x); FMA2(z1, wv.y, a1.y);
            }
#pragma unroll
            for (int i = 0; i < 8; i++) {               // beta region
                ulonglong2 a0 = *(const ulonglong2*)&sact[96 + kq * 40 + 4 * i];
                ulonglong2 a1 = *(const ulonglong2*)&sact[256 + 96 + kq * 40 + 4 * i];
                ulonglong2 wv = *(const ulonglong2*)&sWzb4[((w * 12 + 4 + i) * 32 + lane) * 4];
                FMA2(b0, wv.x, a0.x); FMA2(b0, wv.y, a0.y);
                FMA2(b1, wv.x, a1.x); FMA2(b1, wv.y, a1.y);
            }
            float2 rz0 = upk(z0), rz1 = upk(z1), rb0 = upk(b0), rb1 = upk(b1);
            float zv0 = rz0.x + rz0.y, zv1 = rz1.x + rz1.y;
            float bv0 = rb0.x + rb0.y, bv1 = rb1.x + rb1.y;
#pragma unroll
            for (int off = 1; off <= 2; off <<= 1) {
                zv0 += __shfl_xor_sync(0xffffffffu, zv0, off);
                zv1 += __shfl_xor_sync(0xffffffffu, zv1, off);
                bv0 += __shfl_xor_sync(0xffffffffu, bv0, off);
                bv1 += __shfl_xor_sync(0xffffffffu, bv1, off);
            }
            if (kq < 2) {                                // lane kq -> sample kq
                float zh = (kq ? zv1 : zv0) + sbf[jP];
                float be = sigf((kq ? bv1 : bv0) + sbb[jP]);
                float ch = be * zh + (1.f - be) * xhat[kq * 64 + jP];
                float x = bufc[kq * 64 + jP], m = bufc[128 + kq * 64 + jP];
                actC[ccA] = m * x + (1.f - m) * ch;
                actC[mmA] = m;
                outz[(long)t * 64] = zh;
                outc[(long)t * 64] = ch;
            }
        }
        __syncthreads();

        // ===== P3: LSTM gates, 4 gates/thread, kq quarter-k, 2 passes =====
        {
            float v00, v01, v02, v03, v10, v11, v12, v13;
            // pass sample 0
            {
                ull A0 = 0, A1 = 0, A2 = 0, A3 = 0;
                const float* cp = actC + kq * 56;
#pragma unroll
                for (int i = 0; i < 12; i++) {
                    ulonglong2 L = *(const ulonglong2*)&cp[4 * i];
                    FMA2(A0, wgr[0][2*i], L.x); FMA2(A0, wgr[0][2*i+1], L.y);
                    FMA2(A1, wgr[1][2*i], L.x); FMA2(A1, wgr[1][2*i+1], L.y);
                    FMA2(A2, wgr[2][2*i], L.x); FMA2(A2, wgr[2][2*i+1], L.y);
                    FMA2(A3, wgr[3][2*i], L.x); FMA2(A3, wgr[3][2*i+1], L.y);
                }
                float2 r;
                r = upk(A0); v00 = r.x + r.y;
                r = upk(A1); v01 = r.x + r.y;
                r = upk(A2); v02 = r.x + r.y;
                r = upk(A3); v03 = r.x + r.y;
#pragma unroll
                for (int off = 1; off <= 2; off <<= 1) {
                    v00 += __shfl_xor_sync(0xffffffffu, v00, off);
                    v01 += __shfl_xor_sync(0xffffffffu, v01, off);
                    v02 += __shfl_xor_sync(0xffffffffu, v02, off);
                    v03 += __shfl_xor_sync(0xffffffffu, v03, off);
                }
            }
            // pass sample 1
            {
                ull A0 = 0, A1 = 0, A2 = 0, A3 = 0;
                const float* cp = actC + 224 + kq * 56;
#pragma unroll
                for (int i = 0; i < 12; i++) {
                    ulonglong2 L = *(const ulonglong2*)&cp[4 * i];
                    FMA2(A0, wgr[0][2*i], L.x); FMA2(A0, wgr[0][2*i+1], L.y);
                    FMA2(A1, wgr[1][2*i], L.x); FMA2(A1, wgr[1][2*i+1], L.y);
                    FMA2(A2, wgr[2][2*i], L.x); FMA2(A2, wgr[2][2*i+1], L.y);
                    FMA2(A3, wgr[3][2*i], L.x); FMA2(A3, wgr[3][2*i+1], L.y);
                }
                float2 r;
                r = upk(A0); v10 = r.x + r.y;
                r = upk(A1); v11 = r.x + r.y;
                r = upk(A2); v12 = r.x + r.y;
                r = upk(A3); v13 = r.x + r.y;
#pragma unroll
                for (int off = 1; off <= 2; off <<= 1) {
                    v10 += __shfl_xor_sync(0xffffffffu, v10, off);
                    v11 += __shfl_xor_sync(0xffffffffu, v11, off);
                    v12 += __shfl_xor_sync(0xffffffffu, v12, off);
                    v13 += __shfl_xor_sync(0xffffffffu, v13, off);
                }
            }
            if (kq < 2) {                                // lane kq -> sample kq
                float zi = (kq ? v10 : v00) + bl0;
                float zf = (kq ? v11 : v01) + bl1;
                float zg = (kq ? v12 : v02) + bl2;
                float zo = (kq ? v13 : v03) + bl3;
                float co = cS[kq * 64 + jP];
                float cn = sigf(zf) * co + sigf(zi) * tanhf(zg);
                cS[kq * 64 + jP]   = cn;
                hSp[kq * 80 + jpadP] = sigf(zo) * tanhf(cn);
            }
        }
        if (tid < 192 && t + 1 < TT)
            *(float2*)&inb[(p ^ 1) * 416 + loff] = pf;
        p ^= 1;
        __syncthreads();
    }

    // ===== predictions: sigmoid(h_last @ W_out + b_out) =====
    if (tid < 64) {
        int s = tid >> 5, l = tid & 31;
        float v = hSp[s * 80 + l] * W_out[l] + hSp[s * 80 + 40 + l] * W_out[32 + l];
#pragma unroll
        for (int off = 16; off; off >>= 1)
            v += __shfl_down_sync(0xffffffffu, v, off);
        if (l == 0)
            out[NIMP + 2 * bid + s] = 1.f / (1.f + __expf(-(v + b_out[0])));
    }
}

extern "C" void kernel_launch(void* const* d_in, const int* in_sizes, int n_in,
                              void* d_out, int out_size)
{
    const float* inputs = (const float*)d_in[0];
    const float* W_hist = (const float*)d_in[1];
    const float* b_hist = (const float*)d_in[2];
    const float* W_feat = (const float*)d_in[3];
    const float* b_feat = (const float*)d_in[4];
    const float* W_gx   = (const float*)d_in[5];
    const float* b_gx   = (const float*)d_in[6];
    const float* W_gh   = (const float*)d_in[7];
    const float* b_gh   = (const float*)d_in[8];
    const float* W_beta = (const float*)d_in[9];
    const float* b_beta = (const float*)d_in[10];
    const float* W_lstm = (const float*)d_in[11];
    const float* U_lstm = (const float*)d_in[12];
    const float* b_lstm = (const float*)d_in[13];
    const float* W_out  = (const float*)d_in[14];
    const float* b_out  = (const float*)d_in[15];

    const int smem_bytes = 23072 * (int)sizeof(float);   // 92,288 B
    cudaFuncSetAttribute(rits_kernel,
                         cudaFuncAttributeMaxDynamicSharedMemorySize, smem_bytes);

    rits_kernel<<<128, 256, smem_bytes>>>(
        inputs, W_hist, b_hist, W_feat, b_feat, W_gx, b_gx, W_gh, b_gh,
        W_beta, b_beta, W_lstm, U_lstm, b_lstm, W_out, b_out,
        (float*)d_out);
}